// round 12
// baseline (speedup 1.0000x reference)
#include <cuda_runtime.h>
#include <cstdint>

// ---------------------------------------------------------------------------
// Block-diagonal linear (256x0e+256x1o+256x2e): 3 GEMMs over rows (z,i):
//   A'[z*D+i][u] = feat[z, XOFF + u*D + i];  C = A' * W_b / 16.
// R12 = R10 (cp.async native A + pre-fragmented RNA-tf32 B, 3-stage ring,
// 1 barrier/chunk, 2 CTAs/SM, direct epilogue) MINUS the A-side cvt:
// raw fp32 bits feed mma.sync.tf32 (HW reads the 19 tf32 bits -> bitwise
// truncation). B remains RNA-rounded in the prepass.
// ---------------------------------------------------------------------------
#define HX_BZ   50000
#define HX_FEAT 2304

static constexpr int NTH = 256;   // 8 warps: wm = wid>>1 (4x32 rows), wn = wid&1

// pre-fragmented weights: [b*2+nh][ch][1024 uint4]  (3*2*8*1024 = 49152)
__device__ uint4 g_wfrag[49152];

// ---------------------------------------------------------------------------
__device__ __forceinline__ uint32_t f2tf(float x) {
    uint32_t r;
    asm("cvt.rna.tf32.f32 %0, %1;" : "=r"(r) : "f"(x));
    return r;
}

__device__ __forceinline__ void mma8(float* c, const uint32_t* a,
                                     uint32_t b0, uint32_t b1) {
    asm volatile(
        "mma.sync.aligned.m16n8k8.row.col.f32.tf32.tf32.f32 "
        "{%0,%1,%2,%3}, {%4,%5,%6,%7}, {%8,%9}, {%0,%1,%2,%3};"
        : "+f"(c[0]), "+f"(c[1]), "+f"(c[2]), "+f"(c[3])
        : "r"(a[0]), "r"(a[1]), "r"(a[2]), "r"(a[3]), "r"(b0), "r"(b1));
}

#define CP_A16(dst, src, sz)                                               \
    asm volatile("cp.async.cg.shared.global [%0], [%1], 16, %2;"           \
                 :: "r"(dst), "l"(src), "r"(sz) : "memory")
#define CP_COMMIT() asm volatile("cp.async.commit_group;" ::: "memory")
#define CP_WAIT(n)  asm volatile("cp.async.wait_group %0;" :: "n"(n) : "memory")

__device__ __forceinline__ uint32_t smem_u32(const void* p) {
    uint32_t a;
    asm("{ .reg .u64 t; cvta.to.shared.u64 t, %1; cvt.u32.u64 %0, t; }"
        : "=r"(a) : "l"(p));
    return a;
}

// ---------------------------------------------------------------------------
// Prepass: fragment-order + RNA tf32-round all weights (once, ~3us).
__global__ void prep_w(const float* __restrict__ wt) {
    const int t = blockIdx.x * blockDim.x + threadIdx.x;
    if (t >= 49152) return;
    const int e  = t & 1023;
    const int ch = (t >> 10) & 7;
    const int bn = t >> 13;              // b*2 + nh
    const int b  = bn >> 1, nh = bn & 1;
    const int woff = (b == 0) ? 0 : (b == 1) ? 65536 : 131072;
    const int l5 = e & 31, gg = l5 >> 2, tt = l5 & 3;
    const int blk = e >> 5, nfp = blk & 3, wnn = (blk >> 2) & 1, s = blk >> 3;
    const int k = 32 * ch + 8 * s + tt;
    const int n = 128 * nh + 64 * wnn + 16 * nfp + gg;
    const float* wp = wt + woff + k * 256 + n;
    uint4 q;
    q.x = f2tf(wp[0]);
    q.y = f2tf(wp[1024]);   // k+4
    q.z = f2tf(wp[8]);      // n+8
    q.w = f2tf(wp[1032]);
    g_wfrag[t] = q;
}

// ---------------------------------------------------------------------------
template<int D, int XOFF, int MTOT>
__global__ void __launch_bounds__(NTH, 2)
lin_k(const float* __restrict__ feat, float* __restrict__ out)
{
    constexpr int SD   = (D == 1) ? 36 : (D == 3) ? 104 : 168;
    constexpr int NZ   = (D == 1) ? 128 : (D == 3) ? 44 : 27;
    constexpr int F4Z  = 8 * D;
    constexpr int TOT4 = NZ * F4Z;
    constexpr int PA   = (TOT4 + NTH - 1) / NTH;       // 4 / 5 / 5
    constexpr int ABUF = NZ * SD * 4;                  // bytes per A stage
    constexpr int BOFF = 3 * ABUF;
    constexpr int BBUF = 16384;

    extern __shared__ char smem[];
    const uint32_t smb = smem_u32(smem);

    const int tid  = threadIdx.x;
    const int lane = tid & 31;
    const int wid  = tid >> 5;
    const int g    = lane >> 2;
    const int tg   = lane & 3;
    const int wm   = wid >> 1;
    const int wn   = wid & 1;

    const int bid  = blockIdx.x;
    const int tile = bid >> 1;
    const int nh   = bid & 1;
    const int m0   = tile * 128;
    const int z0   = m0 / D;

    const int bsel = ((D == 1) ? 0 : (D == 3) ? 2 : 4) + nh;
    const char* bbase = (const char*)(g_wfrag + bsel * 8192);

    // ---- A staging decode: PA float4 per thread ----
    const char* asrc[PA];
    uint32_t    adst[PA];
    uint32_t    aszr[PA];
    #pragma unroll
    for (int p = 0; p < PA; p++) {
        const int e  = tid + NTH * p;
        const int zr = e / F4Z;
        const int q  = e - zr * F4Z;
        const int z  = z0 + zr;
        const bool ok = (e < TOT4) && (z < HX_BZ);
        aszr[p] = ok ? 16u : 0u;
        asrc[p] = (const char*)(feat + (size_t)z * HX_FEAT + XOFF) + q * 16;
        adst[p] = (uint32_t)(zr * SD * 4 + q * 16);
        if (e >= TOT4) adst[p] = 0xFFFFFFFFu;
    }

    auto issue = [&](int ch, int st) {
        const uint32_t sa0 = smb + st * ABUF;
        const int aoff = ch * (32 * D) * 4;
        #pragma unroll
        for (int p = 0; p < PA; p++)
            if (adst[p] != 0xFFFFFFFFu)
                CP_A16(sa0 + adst[p], asrc[p] + aoff, aszr[p]);
        const uint32_t sb0 = smb + BOFF + st * BBUF + tid * 16;
        const char* bsrc = bbase + ch * BBUF + tid * 16;
        #pragma unroll
        for (int p = 0; p < 4; p++)
            CP_A16(sb0 + p * (NTH * 16), bsrc + p * (NTH * 16), 16u);
        CP_COMMIT();
    };

    // ---- fragment row decode for A (once per tile) ----
    int arow[2][2];
    #pragma unroll
    for (int mf = 0; mf < 2; mf++)
        #pragma unroll
        for (int hh = 0; hh < 2; hh++) {
            const int r  = wm * 32 + mf * 16 + hh * 8 + g;
            const int gr = m0 + r;
            const int z  = gr / D;
            const int i  = gr - z * D;
            arow[mf][hh] = (z - z0) * SD + i;
        }
    const int tgD = tg * D;

    // ---- accumulators ----
    float c[2][8][4];
    #pragma unroll
    for (int mf = 0; mf < 2; mf++)
        #pragma unroll
        for (int nf = 0; nf < 8; nf++)
            #pragma unroll
            for (int q = 0; q < 4; q++) c[mf][nf][q] = 0.0f;

    auto compute = [&](int st) {
        // A read as raw fp32 bits: HMMA tf32 reads the 19 tf32 bits
        // (bitwise truncation) -> no cvt on the critical path.
        const uint32_t* Af = (const uint32_t*)(smem + st * ABUF);
        const uint4* Bs = (const uint4*)(smem + BOFF + st * BBUF);
        #pragma unroll
        for (int s = 0; s < 4; s++) {
            const int ks = 8 * s * D + tgD;
            uint32_t a[2][4];
            #pragma unroll
            for (int mf = 0; mf < 2; mf++) {
                a[mf][0] = Af[arow[mf][0] + ks];
                a[mf][1] = Af[arow[mf][1] + ks];
                a[mf][2] = Af[arow[mf][0] + ks + 4 * D];
                a[mf][3] = Af[arow[mf][1] + ks + 4 * D];
            }
            #pragma unroll
            for (int nfp = 0; nfp < 4; nfp++) {
                const uint4 b = Bs[((s * 2 + wn) * 4 + nfp) * 32 + lane];
                mma8(c[0][2 * nfp],     a[0], b.x, b.y);
                mma8(c[1][2 * nfp],     a[1], b.x, b.y);
                mma8(c[0][2 * nfp + 1], a[0], b.z, b.w);
                mma8(c[1][2 * nfp + 1], a[1], b.z, b.w);
            }
        }
    };

    // ---- pipeline: joint 3-stage ring, depth-2 prefetch, 1 barrier/chunk --
    issue(0, 0);
    issue(1, 1);
    CP_WAIT(1);
    __syncthreads();

    #pragma unroll 1
    for (int ch = 0; ch < 8; ch++) {
        compute(ch % 3);
        if (ch < 7) {
            if (ch + 2 < 8) {
                issue(ch + 2, (ch + 2) % 3);
                CP_WAIT(1);
            } else {
                CP_WAIT(0);
            }
            __syncthreads();
        }
    }

    // ---- epilogue: direct scatter (R10-proven; repack was neutral) ----
    const float S = 0.0625f;
    #pragma unroll
    for (int mf = 0; mf < 2; mf++) {
        #pragma unroll
        for (int rr = 0; rr < 2; rr++) {
            const int gr = m0 + wm * 32 + mf * 16 + rr * 8 + g;
            if (gr < MTOT) {
                const int z = gr / D;
                const int i = gr - z * D;
                float* op = out + (size_t)z * HX_FEAT + XOFF + i
                          + (size_t)(nh * 128) * D;
                #pragma unroll
                for (int nf = 0; nf < 8; nf++) {
                    const int n = wn * 64 + nf * 8 + 2 * tg;
                    if (D == 1) {
                        float2 v;
                        v.x = c[mf][nf][rr * 2 + 0] * S;
                        v.y = c[mf][nf][rr * 2 + 1] * S;
                        *(float2*)(op + n) = v;
                    } else {
                        op[(size_t)n * D]       = c[mf][nf][rr * 2 + 0] * S;
                        op[(size_t)(n + 1) * D] = c[mf][nf][rr * 2 + 1] * S;
                    }
                }
            }
        }
    }
}

// ---------------------------------------------------------------------------
extern "C" void kernel_launch(void* const* d_in, const int* in_sizes, int n_in,
                              void* d_out, int out_size) {
    const float* feat = (const float*)d_in[0];
    const float* wt   = (const float*)d_in[1];
    float* out        = (float*)d_out;

    constexpr int SM1 = 3 * (128 * 36 * 4) + 3 * 16384;   // 104448
    constexpr int SM3 = 3 * (44 * 104 * 4) + 3 * 16384;   // 104064
    constexpr int SM5 = 3 * (27 * 168 * 4) + 3 * 16384;   // 103584

    auto k1 = lin_k<1, 0,    50000>;
    auto k3 = lin_k<3, 256,  150000>;
    auto k5 = lin_k<5, 1024, 250000>;

    cudaFuncSetAttribute(k1, cudaFuncAttributeMaxDynamicSharedMemorySize, SM1);
    cudaFuncSetAttribute(k3, cudaFuncAttributeMaxDynamicSharedMemorySize, SM3);
    cudaFuncSetAttribute(k5, cudaFuncAttributeMaxDynamicSharedMemorySize, SM5);

    prep_w<<<192, 256>>>(wt);
    k1<<<391 * 2,  NTH, SM1>>>(feat, out);
    k3<<<1172 * 2, NTH, SM3>>>(feat, out);
    k5<<<1954 * 2, NTH, SM5>>>(feat, out);
}

// round 13
// speedup vs baseline: 1.0118x; 1.0118x over previous
#include <cuda_runtime.h>
#include <cstdint>

// ---------------------------------------------------------------------------
// Block-diagonal linear (256x0e+256x1o+256x2e): 3 GEMMs over rows (z,i):
//   A'[z*D+i][u] = feat[z, XOFF + u*D + i];  C = A' * W_b / 16.
// R13 = R12 (cp.async native A, pre-fragmented RNA-tf32 B, truncated-A
// mma feed, 3-stage ring, 2 CTAs/SM) + register-level software pipeline:
// B fragments double-buffered in registers (load s+1 before HMMAs of s),
// staging state compacted to fit the register budget.
// ---------------------------------------------------------------------------
#define HX_BZ   50000
#define HX_FEAT 2304

static constexpr int NTH = 256;   // 8 warps: wm = wid>>1 (4x32 rows), wn = wid&1

// pre-fragmented weights: [b*2+nh][ch][1024 uint4]  (3*2*8*1024 = 49152)
__device__ uint4 g_wfrag[49152];

// ---------------------------------------------------------------------------
__device__ __forceinline__ uint32_t f2tf(float x) {
    uint32_t r;
    asm("cvt.rna.tf32.f32 %0, %1;" : "=r"(r) : "f"(x));
    return r;
}

__device__ __forceinline__ void mma8(float* c, const uint32_t* a,
                                     uint32_t b0, uint32_t b1) {
    asm volatile(
        "mma.sync.aligned.m16n8k8.row.col.f32.tf32.tf32.f32 "
        "{%0,%1,%2,%3}, {%4,%5,%6,%7}, {%8,%9}, {%0,%1,%2,%3};"
        : "+f"(c[0]), "+f"(c[1]), "+f"(c[2]), "+f"(c[3])
        : "r"(a[0]), "r"(a[1]), "r"(a[2]), "r"(a[3]), "r"(b0), "r"(b1));
}

#define CP_A16(dst, src, sz)                                               \
    asm volatile("cp.async.cg.shared.global [%0], [%1], 16, %2;"           \
                 :: "r"(dst), "l"(src), "r"(sz) : "memory")
#define CP_COMMIT() asm volatile("cp.async.commit_group;" ::: "memory")
#define CP_WAIT(n)  asm volatile("cp.async.wait_group %0;" :: "n"(n) : "memory")

__device__ __forceinline__ uint32_t smem_u32(const void* p) {
    uint32_t a;
    asm("{ .reg .u64 t; cvta.to.shared.u64 t, %1; cvt.u32.u64 %0, t; }"
        : "=r"(a) : "l"(p));
    return a;
}

// ---------------------------------------------------------------------------
// Prepass: fragment-order + RNA tf32-round all weights (once, ~3us).
__global__ void prep_w(const float* __restrict__ wt) {
    const int t = blockIdx.x * blockDim.x + threadIdx.x;
    if (t >= 49152) return;
    const int e  = t & 1023;
    const int ch = (t >> 10) & 7;
    const int bn = t >> 13;              // b*2 + nh
    const int b  = bn >> 1, nh = bn & 1;
    const int woff = (b == 0) ? 0 : (b == 1) ? 65536 : 131072;
    const int l5 = e & 31, gg = l5 >> 2, tt = l5 & 3;
    const int blk = e >> 5, nfp = blk & 3, wnn = (blk >> 2) & 1, s = blk >> 3;
    const int k = 32 * ch + 8 * s + tt;
    const int n = 128 * nh + 64 * wnn + 16 * nfp + gg;
    const float* wp = wt + woff + k * 256 + n;
    uint4 q;
    q.x = f2tf(wp[0]);
    q.y = f2tf(wp[1024]);   // k+4
    q.z = f2tf(wp[8]);      // n+8
    q.w = f2tf(wp[1032]);
    g_wfrag[t] = q;
}

// ---------------------------------------------------------------------------
template<int D, int XOFF, int MTOT>
__global__ void __launch_bounds__(NTH, 2)
lin_k(const float* __restrict__ feat, float* __restrict__ out)
{
    constexpr int SD   = (D == 1) ? 36 : (D == 3) ? 104 : 168;
    constexpr int NZ   = (D == 1) ? 128 : (D == 3) ? 44 : 27;
    constexpr int F4Z  = 8 * D;
    constexpr int TOT4 = NZ * F4Z;
    constexpr int PA   = (TOT4 + NTH - 1) / NTH;       // 4 / 5 / 5
    constexpr int ABUF = NZ * SD * 4;                  // bytes per A stage
    constexpr int BOFF = 3 * ABUF;
    constexpr int BBUF = 16384;

    extern __shared__ char smem[];
    const uint32_t smb = smem_u32(smem);

    const int tid  = threadIdx.x;
    const int lane = tid & 31;
    const int wid  = tid >> 5;
    const int g    = lane >> 2;
    const int tg   = lane & 3;
    const int wm   = wid >> 1;
    const int wn   = wid & 1;

    const int bid  = blockIdx.x;
    const int tile = bid >> 1;
    const int nh   = bid & 1;
    const int m0   = tile * 128;
    const int z0   = m0 / D;

    const int bsel = ((D == 1) ? 0 : (D == 3) ? 2 : 4) + nh;
    const char* bbase = (const char*)(g_wfrag + bsel * 8192);

    // ---- A staging decode (compact): smem off (or skip), gmem off (or 0fill)
    uint32_t a_soff[PA];     // 0xFFFFFFFF -> skip entirely
    uint32_t a_goff[PA];     // 0xFFFFFFFF -> zero-fill (size 0 cp.async)
    #pragma unroll
    for (int p = 0; p < PA; p++) {
        const int e  = tid + NTH * p;
        const int zr = e / F4Z;
        const int q  = e - zr * F4Z;
        const int z  = z0 + zr;
        a_soff[p] = (e < TOT4) ? (uint32_t)(zr * SD * 4 + q * 16) : 0xFFFFFFFFu;
        a_goff[p] = (e < TOT4 && z < HX_BZ)
                  ? (uint32_t)((z * HX_FEAT + XOFF + q * 4) * 4) : 0xFFFFFFFFu;
    }

    auto issue = [&](int ch, int st) {
        const uint32_t sa0 = smb + st * ABUF;
        const uint32_t aoff = (uint32_t)(ch * (32 * D) * 4);
        #pragma unroll
        for (int p = 0; p < PA; p++) {
            if (a_soff[p] != 0xFFFFFFFFu) {
                const bool ok = (a_goff[p] != 0xFFFFFFFFu);
                const char* src = (const char*)feat + (ok ? a_goff[p] + aoff : 0u);
                CP_A16(sa0 + a_soff[p], src, ok ? 16u : 0u);
            }
        }
        const uint32_t sb0 = smb + BOFF + st * BBUF + tid * 16;
        const char* bsrc = bbase + ch * BBUF + tid * 16;
        #pragma unroll
        for (int p = 0; p < 4; p++)
            CP_A16(sb0 + p * (NTH * 16), bsrc + p * (NTH * 16), 16u);
        CP_COMMIT();
    };

    // ---- fragment row decode for A (once per tile) ----
    int arow[2][2];
    #pragma unroll
    for (int mf = 0; mf < 2; mf++)
        #pragma unroll
        for (int hh = 0; hh < 2; hh++) {
            const int r  = wm * 32 + mf * 16 + hh * 8 + g;
            const int gr = m0 + r;
            const int z  = gr / D;
            const int i  = gr - z * D;
            arow[mf][hh] = (z - z0) * SD + i;
        }
    const int tgD = tg * D;

    // ---- accumulators ----
    float c[2][8][4];
    #pragma unroll
    for (int mf = 0; mf < 2; mf++)
        #pragma unroll
        for (int nf = 0; nf < 8; nf++)
            #pragma unroll
            for (int q = 0; q < 4; q++) c[mf][nf][q] = 0.0f;

    auto compute = [&](int st) {
        const uint32_t* Af = (const uint32_t*)(smem + st * ABUF);
        const uint4* Bs = (const uint4*)(smem + BOFF + st * BBUF);
        // register-level software pipeline on B fragments
        uint4 bf[2][4];
        #pragma unroll
        for (int nfp = 0; nfp < 4; nfp++)
            bf[0][nfp] = Bs[((/*s=*/0 * 2 + wn) * 4 + nfp) * 32 + lane];
        #pragma unroll
        for (int s = 0; s < 4; s++) {
            const int cur = s & 1;
            const int ks = 8 * s * D + tgD;
            uint32_t a[2][4];
            #pragma unroll
            for (int mf = 0; mf < 2; mf++) {
                a[mf][0] = Af[arow[mf][0] + ks];
                a[mf][1] = Af[arow[mf][1] + ks];
                a[mf][2] = Af[arow[mf][0] + ks + 4 * D];
                a[mf][3] = Af[arow[mf][1] + ks + 4 * D];
            }
            if (s < 3) {
                #pragma unroll
                for (int nfp = 0; nfp < 4; nfp++)
                    bf[cur ^ 1][nfp] =
                        Bs[(((s + 1) * 2 + wn) * 4 + nfp) * 32 + lane];
            }
            #pragma unroll
            for (int nfp = 0; nfp < 4; nfp++) {
                const uint4 b = bf[cur][nfp];
                mma8(c[0][2 * nfp],     a[0], b.x, b.y);
                mma8(c[1][2 * nfp],     a[1], b.x, b.y);
                mma8(c[0][2 * nfp + 1], a[0], b.z, b.w);
                mma8(c[1][2 * nfp + 1], a[1], b.z, b.w);
            }
        }
    };

    // ---- pipeline: joint 3-stage ring, depth-2 prefetch, 1 barrier/chunk --
    issue(0, 0);
    issue(1, 1);
    CP_WAIT(1);
    __syncthreads();

    #pragma unroll 1
    for (int ch = 0; ch < 8; ch++) {
        compute(ch % 3);
        if (ch < 7) {
            if (ch + 2 < 8) {
                issue(ch + 2, (ch + 2) % 3);
                CP_WAIT(1);
            } else {
                CP_WAIT(0);
            }
            __syncthreads();
        }
    }

    // ---- epilogue: direct scatter (repack proven neutral in R11) ----
    const float S = 0.0625f;
    #pragma unroll
    for (int mf = 0; mf < 2; mf++) {
        #pragma unroll
        for (int rr = 0; rr < 2; rr++) {
            const int gr = m0 + wm * 32 + mf * 16 + rr * 8 + g;
            if (gr < MTOT) {
                const int z = gr / D;
                const int i = gr - z * D;
                float* op = out + (size_t)z * HX_FEAT + XOFF + i
                          + (size_t)(nh * 128) * D;
                #pragma unroll
                for (int nf = 0; nf < 8; nf++) {
                    const int n = wn * 64 + nf * 8 + 2 * tg;
                    if (D == 1) {
                        float2 v;
                        v.x = c[mf][nf][rr * 2 + 0] * S;
                        v.y = c[mf][nf][rr * 2 + 1] * S;
                        *(float2*)(op + n) = v;
                    } else {
                        op[(size_t)n * D]       = c[mf][nf][rr * 2 + 0] * S;
                        op[(size_t)(n + 1) * D] = c[mf][nf][rr * 2 + 1] * S;
                    }
                }
            }
        }
    }
}

// ---------------------------------------------------------------------------
extern "C" void kernel_launch(void* const* d_in, const int* in_sizes, int n_in,
                              void* d_out, int out_size) {
    const float* feat = (const float*)d_in[0];
    const float* wt   = (const float*)d_in[1];
    float* out        = (float*)d_out;

    constexpr int SM1 = 3 * (128 * 36 * 4) + 3 * 16384;   // 104448
    constexpr int SM3 = 3 * (44 * 104 * 4) + 3 * 16384;   // 104064
    constexpr int SM5 = 3 * (27 * 168 * 4) + 3 * 16384;   // 103584

    auto k1 = lin_k<1, 0,    50000>;
    auto k3 = lin_k<3, 256,  150000>;
    auto k5 = lin_k<5, 1024, 250000>;

    cudaFuncSetAttribute(k1, cudaFuncAttributeMaxDynamicSharedMemorySize, SM1);
    cudaFuncSetAttribute(k3, cudaFuncAttributeMaxDynamicSharedMemorySize, SM3);
    cudaFuncSetAttribute(k5, cudaFuncAttributeMaxDynamicSharedMemorySize, SM5);

    prep_w<<<192, 256>>>(wt);
    k1<<<391 * 2,  NTH, SM1>>>(feat, out);
    k3<<<1172 * 2, NTH, SM3>>>(feat, out);
    k5<<<1954 * 2, NTH, SM5>>>(feat, out);
}

// round 14
// speedup vs baseline: 1.0459x; 1.0337x over previous
#include <cuda_runtime.h>
#include <cstdint>

// ---------------------------------------------------------------------------
// Block-diagonal linear (256x0e+256x1o+256x2e): 3 GEMMs over rows (z,i):
//   A'[z*D+i][u] = feat[z, XOFF + u*D + i];  C = A' * W_b / 16.
// R14: 128-thread CTAs (4 warps, warp tile 64x64, P=Q=2) -> smem crossbar
// traffic per chunk drops 33% (replication (P+Q): 6 -> 4). 2 CTAs/SM via
// __launch_bounds__(128,2) (reg cap 256: 128 accum + operands fit, no spill).
// Rest identical to R12/R13: cp.async native-layout A, pre-fragmented
// RNA-tf32 B (prepass), truncated-A mma feed, 3-stage ring, 1 barrier/chunk.
// ---------------------------------------------------------------------------
#define HX_BZ   50000
#define HX_FEAT 2304

static constexpr int NTH = 128;   // 4 warps: wm = wid&1 (2x64 rows), wn = wid>>1

// pre-fragmented weights: [b*2+nh][ch][1024 uint4]  (3*2*8*1024 = 49152)
__device__ uint4 g_wfrag[49152];

// ---------------------------------------------------------------------------
__device__ __forceinline__ uint32_t f2tf(float x) {
    uint32_t r;
    asm("cvt.rna.tf32.f32 %0, %1;" : "=r"(r) : "f"(x));
    return r;
}

__device__ __forceinline__ void mma8(float* c, const uint32_t* a,
                                     uint32_t b0, uint32_t b1) {
    asm volatile(
        "mma.sync.aligned.m16n8k8.row.col.f32.tf32.tf32.f32 "
        "{%0,%1,%2,%3}, {%4,%5,%6,%7}, {%8,%9}, {%0,%1,%2,%3};"
        : "+f"(c[0]), "+f"(c[1]), "+f"(c[2]), "+f"(c[3])
        : "r"(a[0]), "r"(a[1]), "r"(a[2]), "r"(a[3]), "r"(b0), "r"(b1));
}

#define CP_A16(dst, src, sz)                                               \
    asm volatile("cp.async.cg.shared.global [%0], [%1], 16, %2;"           \
                 :: "r"(dst), "l"(src), "r"(sz) : "memory")
#define CP_COMMIT() asm volatile("cp.async.commit_group;" ::: "memory")
#define CP_WAIT(n)  asm volatile("cp.async.wait_group %0;" :: "n"(n) : "memory")

__device__ __forceinline__ uint32_t smem_u32(const void* p) {
    uint32_t a;
    asm("{ .reg .u64 t; cvta.to.shared.u64 t, %1; cvt.u32.u64 %0, t; }"
        : "=r"(a) : "l"(p));
    return a;
}

// ---------------------------------------------------------------------------
// Prepass: fragment-order + RNA tf32-round all weights (once, ~3us).
__global__ void prep_w(const float* __restrict__ wt) {
    const int t = blockIdx.x * blockDim.x + threadIdx.x;
    if (t >= 49152) return;
    const int e  = t & 1023;
    const int ch = (t >> 10) & 7;
    const int bn = t >> 13;              // b*2 + nh
    const int b  = bn >> 1, nh = bn & 1;
    const int woff = (b == 0) ? 0 : (b == 1) ? 65536 : 131072;
    const int l5 = e & 31, gg = l5 >> 2, tt = l5 & 3;
    const int blk = e >> 5, nfp = blk & 3, wnn = (blk >> 2) & 1, s = blk >> 3;
    const int k = 32 * ch + 8 * s + tt;
    const int n = 128 * nh + 64 * wnn + 16 * nfp + gg;
    const float* wp = wt + woff + k * 256 + n;
    uint4 q;
    q.x = f2tf(wp[0]);
    q.y = f2tf(wp[1024]);   // k+4
    q.z = f2tf(wp[8]);      // n+8
    q.w = f2tf(wp[1032]);
    g_wfrag[t] = q;
}

// ---------------------------------------------------------------------------
template<int D, int XOFF, int MTOT>
__global__ void __launch_bounds__(NTH, 2)
lin_k(const float* __restrict__ feat, float* __restrict__ out)
{
    constexpr int SD   = (D == 1) ? 36 : (D == 3) ? 104 : 168;
    constexpr int NZ   = (D == 1) ? 128 : (D == 3) ? 44 : 27;
    constexpr int F4Z  = 8 * D;
    constexpr int TOT4 = NZ * F4Z;                     // 1024 / 1056 / 1080
    constexpr int PA   = (TOT4 + NTH - 1) / NTH;       // 8 / 9 / 9
    constexpr int ABUF = NZ * SD * 4;                  // bytes per A stage
    constexpr int BOFF = 3 * ABUF;
    constexpr int BBUF = 16384;

    extern __shared__ char smem[];
    const uint32_t smb = smem_u32(smem);

    const int tid  = threadIdx.x;
    const int lane = tid & 31;
    const int wid  = tid >> 5;
    const int g    = lane >> 2;
    const int tg   = lane & 3;
    const int wm   = wid & 1;      // 2 x 64 rows
    const int wn   = wid >> 1;     // 2 x 64 cols

    const int bid  = blockIdx.x;
    const int tile = bid >> 1;
    const int nh   = bid & 1;
    const int m0   = tile * 128;
    const int z0   = m0 / D;

    const int bsel = ((D == 1) ? 0 : (D == 3) ? 2 : 4) + nh;
    const char* bbase = (const char*)(g_wfrag + bsel * 8192);

    // ---- A staging decode (compact): smem off (or skip), gmem off (or 0fill)
    uint32_t a_soff[PA];     // 0xFFFFFFFF -> skip entirely
    uint32_t a_goff[PA];     // 0xFFFFFFFF -> zero-fill (size 0 cp.async)
    #pragma unroll
    for (int p = 0; p < PA; p++) {
        const int e  = tid + NTH * p;
        const int zr = e / F4Z;
        const int q  = e - zr * F4Z;
        const int z  = z0 + zr;
        a_soff[p] = (e < TOT4) ? (uint32_t)(zr * SD * 4 + q * 16) : 0xFFFFFFFFu;
        a_goff[p] = (e < TOT4 && z < HX_BZ)
                  ? (uint32_t)((z * HX_FEAT + XOFF + q * 4) * 4) : 0xFFFFFFFFu;
    }

    auto issue = [&](int ch, int st) {
        const uint32_t sa0 = smb + st * ABUF;
        const uint32_t aoff = (uint32_t)(ch * (32 * D) * 4);
        #pragma unroll
        for (int p = 0; p < PA; p++) {
            if (a_soff[p] != 0xFFFFFFFFu) {
                const bool ok = (a_goff[p] != 0xFFFFFFFFu);
                const char* src = (const char*)feat + (ok ? a_goff[p] + aoff : 0u);
                CP_A16(sa0 + a_soff[p], src, ok ? 16u : 0u);
            }
        }
        const uint32_t sb0 = smb + BOFF + st * BBUF + tid * 16;
        const char* bsrc = bbase + ch * BBUF + tid * 16;
        #pragma unroll
        for (int p = 0; p < 8; p++)
            CP_A16(sb0 + p * (NTH * 16), bsrc + p * (NTH * 16), 16u);
        CP_COMMIT();
    };

    // ---- fragment row decode for A (once per tile) ----
    int arow[4][2];
    #pragma unroll
    for (int mf = 0; mf < 4; mf++)
        #pragma unroll
        for (int hh = 0; hh < 2; hh++) {
            const int r  = wm * 64 + mf * 16 + hh * 8 + g;
            const int gr = m0 + r;
            const int z  = gr / D;
            const int i  = gr - z * D;
            arow[mf][hh] = (z - z0) * SD + i;
        }
    const int tgD = tg * D;

    // ---- accumulators: 4 m-frags x 8 n-frags ----
    float c[4][8][4];
    #pragma unroll
    for (int mf = 0; mf < 4; mf++)
        #pragma unroll
        for (int nf = 0; nf < 8; nf++)
            #pragma unroll
            for (int q = 0; q < 4; q++) c[mf][nf][q] = 0.0f;

    auto compute = [&](int st) {
        // A fed as raw fp32 bits (HW truncates to tf32); B pre-rounded RNA.
        const uint32_t* Af = (const uint32_t*)(smem + st * ABUF);
        const uint4* Bs = (const uint4*)(smem + BOFF + st * BBUF);
        #pragma unroll
        for (int s = 0; s < 4; s++) {
            const int ks = 8 * s * D + tgD;
            uint32_t a[4][4];
            #pragma unroll
            for (int mf = 0; mf < 4; mf++) {
                a[mf][0] = Af[arow[mf][0] + ks];
                a[mf][1] = Af[arow[mf][1] + ks];
                a[mf][2] = Af[arow[mf][0] + ks + 4 * D];
                a[mf][3] = Af[arow[mf][1] + ks + 4 * D];
            }
            #pragma unroll
            for (int nfp = 0; nfp < 4; nfp++) {
                const uint4 b = Bs[((s * 2 + wn) * 4 + nfp) * 32 + lane];
                #pragma unroll
                for (int mf = 0; mf < 4; mf++) {
                    mma8(c[mf][2 * nfp],     a[mf], b.x, b.y);
                    mma8(c[mf][2 * nfp + 1], a[mf], b.z, b.w);
                }
            }
        }
    };

    // ---- pipeline: joint 3-stage ring, depth-2 prefetch, 1 barrier/chunk --
    issue(0, 0);
    issue(1, 1);
    CP_WAIT(1);
    __syncthreads();

    #pragma unroll 1
    for (int ch = 0; ch < 8; ch++) {
        compute(ch % 3);
        if (ch < 7) {
            if (ch + 2 < 8) {
                issue(ch + 2, (ch + 2) % 3);
                CP_WAIT(1);
            } else {
                CP_WAIT(0);
            }
            __syncthreads();
        }
    }

    // ---- epilogue: direct scatter (repack proven neutral in R11) ----
    const float S = 0.0625f;
    #pragma unroll
    for (int mf = 0; mf < 4; mf++) {
        #pragma unroll
        for (int rr = 0; rr < 2; rr++) {
            const int gr = m0 + wm * 64 + mf * 16 + rr * 8 + g;
            if (gr < MTOT) {
                const int z = gr / D;
                const int i = gr - z * D;
                float* op = out + (size_t)z * HX_FEAT + XOFF + i
                          + (size_t)(nh * 128) * D;
                #pragma unroll
                for (int nf = 0; nf < 8; nf++) {
                    const int n = wn * 64 + (nf >> 1) * 16 + (nf & 1) * 8 + 2 * tg;
                    if (D == 1) {
                        float2 v;
                        v.x = c[mf][nf][rr * 2 + 0] * S;
                        v.y = c[mf][nf][rr * 2 + 1] * S;
                        *(float2*)(op + n) = v;
                    } else {
                        op[(size_t)n * D]       = c[mf][nf][rr * 2 + 0] * S;
                        op[(size_t)(n + 1) * D] = c[mf][nf][rr * 2 + 1] * S;
                    }
                }
            }
        }
    }
}

// ---------------------------------------------------------------------------
extern "C" void kernel_launch(void* const* d_in, const int* in_sizes, int n_in,
                              void* d_out, int out_size) {
    const float* feat = (const float*)d_in[0];
    const float* wt   = (const float*)d_in[1];
    float* out        = (float*)d_out;

    constexpr int SM1 = 3 * (128 * 36 * 4) + 3 * 16384;   // 104448
    constexpr int SM3 = 3 * (44 * 104 * 4) + 3 * 16384;   // 104064
    constexpr int SM5 = 3 * (27 * 168 * 4) + 3 * 16384;   // 103584

    auto k1 = lin_k<1, 0,    50000>;
    auto k3 = lin_k<3, 256,  150000>;
    auto k5 = lin_k<5, 1024, 250000>;

    cudaFuncSetAttribute(k1, cudaFuncAttributeMaxDynamicSharedMemorySize, SM1);
    cudaFuncSetAttribute(k3, cudaFuncAttributeMaxDynamicSharedMemorySize, SM3);
    cudaFuncSetAttribute(k5, cudaFuncAttributeMaxDynamicSharedMemorySize, SM5);

    prep_w<<<192, 256>>>(wt);
    k1<<<391 * 2,  NTH, SM1>>>(feat, out);
    k3<<<1172 * 2, NTH, SM3>>>(feat, out);
    k5<<<1954 * 2, NTH, SM5>>>(feat, out);
}

// round 15
// speedup vs baseline: 1.3503x; 1.2910x over previous
#include <cuda_runtime.h>
#include <cuda_fp16.h>
#include <cstdint>

// ---------------------------------------------------------------------------
// Block-diagonal linear (256x0e+256x1o+256x2e): 3 GEMMs over rows (z,i):
//   A'[z*D+i][u] = feat[z, XOFF + u*D + i];  C = A' * W_b / 16.
// R15 = R14 skeleton (128-thr CTAs, 2/SM, warp 64x64, cp.async native fp32 A,
// pre-fragmented B prepass, 3-stage ring, 1 barrier/chunk) switched to
// fp16 mma.sync.m16n8k16 (2x the tf32 HMMA rate; fp16 mantissa == tf32
// mantissa, inputs N(0,1) are range-safe, accumulation stays fp32).
// B prepass emits RN fp16 fragments; A converted in-loop (floats2half2_rn).
// ---------------------------------------------------------------------------
#define HX_BZ   50000
#define HX_FEAT 2304

static constexpr int NTH = 128;   // 4 warps: wm = wid&1 (2x64 rows), wn = wid>>1

// pre-fragmented fp16 weights: [b*2+nh][ch(8)][512 uint4] = 24576 uint4
__device__ uint4 g_wfrag[24576];

// ---------------------------------------------------------------------------
__device__ __forceinline__ uint32_t pack2(float lo, float hi) {
    __half2 h = __floats2half2_rn(lo, hi);   // low half = lo (lower k)
    return *(uint32_t*)&h;
}

__device__ __forceinline__ void mma16(float* c, const uint32_t* a,
                                      uint32_t b0, uint32_t b1) {
    asm volatile(
        "mma.sync.aligned.m16n8k16.row.col.f32.f16.f16.f32 "
        "{%0,%1,%2,%3}, {%4,%5,%6,%7}, {%8,%9}, {%0,%1,%2,%3};"
        : "+f"(c[0]), "+f"(c[1]), "+f"(c[2]), "+f"(c[3])
        : "r"(a[0]), "r"(a[1]), "r"(a[2]), "r"(a[3]), "r"(b0), "r"(b1));
}

#define CP_A16(dst, src, sz)                                               \
    asm volatile("cp.async.cg.shared.global [%0], [%1], 16, %2;"           \
                 :: "r"(dst), "l"(src), "r"(sz) : "memory")
#define CP_COMMIT() asm volatile("cp.async.commit_group;" ::: "memory")
#define CP_WAIT(n)  asm volatile("cp.async.wait_group %0;" :: "n"(n) : "memory")

__device__ __forceinline__ uint32_t smem_u32(const void* p) {
    uint32_t a;
    asm("{ .reg .u64 t; cvta.to.shared.u64 t, %1; cvt.u32.u64 %0, t; }"
        : "=r"(a) : "l"(p));
    return a;
}

// ---------------------------------------------------------------------------
// Prepass: RN-fp16 + fragment-order all weights (once, ~3us).
// t = bn*4096 + ch*512 + e,  e = ((s*2+wn)*4+nfp)*32 + lane
__global__ void prep_w(const float* __restrict__ wt) {
    const int t = blockIdx.x * blockDim.x + threadIdx.x;
    if (t >= 24576) return;
    const int e  = t & 511;
    const int ch = (t >> 9) & 7;
    const int bn = t >> 12;              // b*2 + nh
    const int b  = bn >> 1, nh = bn & 1;
    const int woff = (b == 0) ? 0 : (b == 1) ? 65536 : 131072;
    const int lane = e & 31, g = lane >> 2, tg = lane & 3;
    const int idx = e >> 5;              // 0..15
    const int nfp = idx & 3, wn = (idx >> 2) & 1, s = idx >> 3;
    const int k0 = 32 * ch + 16 * s + 2 * tg;
    const int n  = 128 * nh + 64 * wn + 16 * nfp + g;
    const float* wp = wt + woff;
    uint4 q;
    q.x = pack2(wp[k0 * 256 + n],           wp[(k0 + 1) * 256 + n]);
    q.y = pack2(wp[(k0 + 8) * 256 + n],     wp[(k0 + 9) * 256 + n]);
    q.z = pack2(wp[k0 * 256 + n + 8],       wp[(k0 + 1) * 256 + n + 8]);
    q.w = pack2(wp[(k0 + 8) * 256 + n + 8], wp[(k0 + 9) * 256 + n + 8]);
    g_wfrag[t] = q;
}

// ---------------------------------------------------------------------------
template<int D, int XOFF, int MTOT>
__global__ void __launch_bounds__(NTH, 2)
lin_k(const float* __restrict__ feat, float* __restrict__ out)
{
    // A native fp32 layout: per z row, stride SD floats
    // (D=1: 40 -> float2 frag loads conflict-free; D>1 as before)
    constexpr int SD   = (D == 1) ? 40 : (D == 3) ? 104 : 168;
    constexpr int NZ   = (D == 1) ? 128 : (D == 3) ? 44 : 27;
    constexpr int F4Z  = 8 * D;
    constexpr int TOT4 = NZ * F4Z;
    constexpr int PA   = (TOT4 + NTH - 1) / NTH;       // 8 / 9 / 9
    constexpr int ABUF = NZ * SD * 4;
    constexpr int BOFF = 3 * ABUF;
    constexpr int BBUF = 8192;                         // fp16 B chunk

    extern __shared__ char smem[];
    const uint32_t smb = smem_u32(smem);

    const int tid  = threadIdx.x;
    const int lane = tid & 31;
    const int wid  = tid >> 5;
    const int g    = lane >> 2;
    const int tg   = lane & 3;
    const int wm   = wid & 1;      // 2 x 64 rows
    const int wn   = wid >> 1;     // 2 x 64 cols

    const int bid  = blockIdx.x;
    const int tile = bid >> 1;
    const int nh   = bid & 1;
    const int m0   = tile * 128;
    const int z0   = m0 / D;

    const int bsel = ((D == 1) ? 0 : (D == 3) ? 2 : 4) + nh;
    const char* bbase = (const char*)(g_wfrag + bsel * 4096);

    // ---- A staging decode (compact) ----
    uint32_t a_soff[PA];     // 0xFFFFFFFF -> skip
    uint32_t a_goff[PA];     // 0xFFFFFFFF -> zero-fill
    #pragma unroll
    for (int p = 0; p < PA; p++) {
        const int e  = tid + NTH * p;
        const int zr = e / F4Z;
        const int q  = e - zr * F4Z;
        const int z  = z0 + zr;
        a_soff[p] = (e < TOT4) ? (uint32_t)(zr * SD * 4 + q * 16) : 0xFFFFFFFFu;
        a_goff[p] = (e < TOT4 && z < HX_BZ)
                  ? (uint32_t)((z * HX_FEAT + XOFF + q * 4) * 4) : 0xFFFFFFFFu;
    }

    auto issue = [&](int ch, int st) {
        const uint32_t sa0 = smb + st * ABUF;
        const uint32_t aoff = (uint32_t)(ch * (32 * D) * 4);
        #pragma unroll
        for (int p = 0; p < PA; p++) {
            if (a_soff[p] != 0xFFFFFFFFu) {
                const bool ok = (a_goff[p] != 0xFFFFFFFFu);
                const char* src = (const char*)feat + (ok ? a_goff[p] + aoff : 0u);
                CP_A16(sa0 + a_soff[p], src, ok ? 16u : 0u);
            }
        }
        const uint32_t sb0 = smb + BOFF + st * BBUF + tid * 16;
        const char* bsrc = bbase + ch * BBUF + tid * 16;
        #pragma unroll
        for (int p = 0; p < 4; p++)
            CP_A16(sb0 + p * (NTH * 16), bsrc + p * (NTH * 16), 16u);
        CP_COMMIT();
    };

    // ---- fragment row decode for A (once per tile) ----
    int arow[4][2];
    #pragma unroll
    for (int mf = 0; mf < 4; mf++)
        #pragma unroll
        for (int hh = 0; hh < 2; hh++) {
            const int r  = wm * 64 + mf * 16 + hh * 8 + g;
            const int gr = m0 + r;
            const int z  = gr / D;
            const int i  = gr - z * D;
            arow[mf][hh] = (z - z0) * SD + i;
        }

    // ---- accumulators: 4 m-frags x 8 n-frags ----
    float c[4][8][4];
    #pragma unroll
    for (int mf = 0; mf < 4; mf++)
        #pragma unroll
        for (int nf = 0; nf < 8; nf++)
            #pragma unroll
            for (int q = 0; q < 4; q++) c[mf][nf][q] = 0.0f;

    auto compute = [&](int st) {
        const float* Af = (const float*)(smem + st * ABUF);
        const uint4* Bs = (const uint4*)(smem + BOFF + st * BBUF);
        #pragma unroll
        for (int s = 0; s < 2; s++) {            // two k16 steps per chunk
            uint32_t a[4][4];
            #pragma unroll
            for (int mf = 0; mf < 4; mf++) {
                if (D == 1) {
                    const int kb = 16 * s + 2 * tg;
                    const float2 p00 = *(const float2*)&Af[arow[mf][0] + kb];
                    const float2 p10 = *(const float2*)&Af[arow[mf][1] + kb];
                    const float2 p01 = *(const float2*)&Af[arow[mf][0] + kb + 8];
                    const float2 p11 = *(const float2*)&Af[arow[mf][1] + kb + 8];
                    a[mf][0] = pack2(p00.x, p00.y);
                    a[mf][1] = pack2(p10.x, p10.y);
                    a[mf][2] = pack2(p01.x, p01.y);
                    a[mf][3] = pack2(p11.x, p11.y);
                } else {
                    const int kb = (16 * s + 2 * tg) * D;
                    const int r0 = arow[mf][0], r1 = arow[mf][1];
                    a[mf][0] = pack2(Af[r0 + kb],         Af[r0 + kb + D]);
                    a[mf][1] = pack2(Af[r1 + kb],         Af[r1 + kb + D]);
                    a[mf][2] = pack2(Af[r0 + kb + 8 * D], Af[r0 + kb + 9 * D]);
                    a[mf][3] = pack2(Af[r1 + kb + 8 * D], Af[r1 + kb + 9 * D]);
                }
            }
            #pragma unroll
            for (int nfp = 0; nfp < 4; nfp++) {
                const uint4 b = Bs[((s * 2 + wn) * 4 + nfp) * 32 + lane];
                #pragma unroll
                for (int mf = 0; mf < 4; mf++) {
                    mma16(c[mf][2 * nfp],     a[mf], b.x, b.y);
                    mma16(c[mf][2 * nfp + 1], a[mf], b.z, b.w);
                }
            }
        }
    };

    // ---- pipeline: joint 3-stage ring, depth-2 prefetch, 1 barrier/chunk --
    issue(0, 0);
    issue(1, 1);
    CP_WAIT(1);
    __syncthreads();

    #pragma unroll 1
    for (int ch = 0; ch < 8; ch++) {
        compute(ch % 3);
        if (ch < 7) {
            if (ch + 2 < 8) {
                issue(ch + 2, (ch + 2) % 3);
                CP_WAIT(1);
            } else {
                CP_WAIT(0);
            }
            __syncthreads();
        }
    }

    // ---- epilogue: direct scatter, scale 1/sqrt(256) ----
    const float S = 0.0625f;
    #pragma unroll
    for (int mf = 0; mf < 4; mf++) {
        #pragma unroll
        for (int rr = 0; rr < 2; rr++) {
            const int gr = m0 + wm * 64 + mf * 16 + rr * 8 + g;
            if (gr < MTOT) {
                const int z = gr / D;
                const int i = gr - z * D;
                float* op = out + (size_t)z * HX_FEAT + XOFF + i
                          + (size_t)(nh * 128) * D;
                #pragma unroll
                for (int nf = 0; nf < 8; nf++) {
                    const int n = wn * 64 + (nf >> 1) * 16 + (nf & 1) * 8 + 2 * tg;
                    if (D == 1) {
                        float2 v;
                        v.x = c[mf][nf][rr * 2 + 0] * S;
                        v.y = c[mf][nf][rr * 2 + 1] * S;
                        *(float2*)(op + n) = v;
                    } else {
                        op[(size_t)n * D]       = c[mf][nf][rr * 2 + 0] * S;
                        op[(size_t)(n + 1) * D] = c[mf][nf][rr * 2 + 1] * S;
                    }
                }
            }
        }
    }
}

// ---------------------------------------------------------------------------
extern "C" void kernel_launch(void* const* d_in, const int* in_sizes, int n_in,
                              void* d_out, int out_size) {
    const float* feat = (const float*)d_in[0];
    const float* wt   = (const float*)d_in[1];
    float* out        = (float*)d_out;

    constexpr int SM1 = 3 * (128 * 40 * 4) + 3 * 8192;   // 86016
    constexpr int SM3 = 3 * (44 * 104 * 4) + 3 * 8192;   // 79488
    constexpr int SM5 = 3 * (27 * 168 * 4) + 3 * 8192;   // 78912

    auto k1 = lin_k<1, 0,    50000>;
    auto k3 = lin_k<3, 256,  150000>;
    auto k5 = lin_k<5, 1024, 250000>;

    cudaFuncSetAttribute(k1, cudaFuncAttributeMaxDynamicSharedMemorySize, SM1);
    cudaFuncSetAttribute(k3, cudaFuncAttributeMaxDynamicSharedMemorySize, SM3);
    cudaFuncSetAttribute(k5, cudaFuncAttributeMaxDynamicSharedMemorySize, SM5);

    prep_w<<<96, 256>>>(wt);
    k1<<<391 * 2,  NTH, SM1>>>(feat, out);
    k3<<<1172 * 2, NTH, SM3>>>(feat, out);
    k5<<<1954 * 2, NTH, SM5>>>(feat, out);
}